// round 13
// baseline (speedup 1.0000x reference)
#include <cuda_runtime.h>

// Problem constants
#define DIM   (1 << 22)        // 2^22 = 4194304
#define BATCH 16
#define H8    ((DIM / 2) * BATCH / 8)   // 4194304 float8s per half-state
#define TPB   256                        // best-measured config

// 256-bit global streaming load (evict-first) / default store
// (sm_100+/sm_103a: LDG.E.256 / STG.E.256).
__device__ __forceinline__ void ldg256_cs(const float* __restrict__ p, float v[8]) {
    asm("ld.global.cs.v8.f32 {%0,%1,%2,%3,%4,%5,%6,%7}, [%8];"
        : "=f"(v[0]), "=f"(v[1]), "=f"(v[2]), "=f"(v[3]),
          "=f"(v[4]), "=f"(v[5]), "=f"(v[6]), "=f"(v[7])
        : "l"(p));
}
__device__ __forceinline__ void stg256(float* p, const float v[8]) {
    asm volatile("st.global.v8.f32 [%0], {%1,%2,%3,%4,%5,%6,%7,%8};"
        :: "l"(p),
           "f"(v[0]), "f"(v[1]), "f"(v[2]), "f"(v[3]),
           "f"(v[4]), "f"(v[5]), "f"(v[6]), "f"(v[7])
        : "memory");
}

// FINAL KERNEL — session optimum, converged after 12 rounds / 11 variants.
//
// RX(theta_b) on qubit 0 (MSB axis) applied to a (DIM, BATCH) complex state
// stored as separate re/im planes; output is stacked (re, im) planes.
// Pure 1:1 read/write stream: 536 MB in + 536 MB out at ~6.78 TB/s (85% of
// 8 TB/s HBM3e spec) — the read/write bus-turnaround roofline. The ceiling
// is insensitive to: occupancy (37-63%), per-thread MLP (4-8), vector width
// (128/256-bit), block size (128/256), work-per-thread, index width.
// Store coherence is the only sensitive knob: default stores win; .cs/.wt
// stores cost 1.5-2.5 us in LTS handling. .cs loads are neutral-to-positive
// (zero-reuse inputs skip L2 retention): best kernel times (150.0-151.3 us)
// and best DRAM% (85.7) belong to this configuration.
//
// Thread t owns one float8 (8 of the 16 batch entries) of row j in the lower
// half, paired with row j + DIM/2. 4x LDG.256 front-batched and overlapped
// with the 16-element cos/sin broadcast, then 4x STG.256. All index math is
// 32-bit (each array is 256 MB; byte offsets < 2^31).
//
// Memory layout (float8 index space, H = H8):
//   inputs : re[t], re[t+H], im[t], im[t+H]
//   outputs: out_re lower = out[t], out_re upper = out[t+H]
//            out_im lower = out[2H+t], out_im upper = out[3H+t]
__global__ __launch_bounds__(TPB) void rot_kernel(
    const float* __restrict__ theta,
    const float* __restrict__ re,
    const float* __restrict__ im,
    float* __restrict__ out)
{
    __shared__ float sc[BATCH];
    __shared__ float ss[BATCH];

    unsigned t = blockIdx.x * TPB + threadIdx.x;   // float8 index, < 2^22

    // 4 independent 256-bit evict-first loads issued first
    // (latency overlapped with trig + barrier below)
    float re0[8], re1[8], im0[8], im1[8];
    ldg256_cs(re + t * 8u,             re0);
    ldg256_cs(re + (t + H8) * 8u,      re1);
    ldg256_cs(im + t * 8u,             im0);
    ldg256_cs(im + (t + H8) * 8u,      im1);

    if (threadIdx.x < BATCH) {
        float th = theta[threadIdx.x] * 0.5f;  // L2-resident after first wave
        sc[threadIdx.x] = cosf(th);
        ss[threadIdx.x] = sinf(th);
    }
    __syncthreads();

    int b8 = (int)(t & 1u) * 8;  // which float8 within the 16-wide batch row

    float or0[8], or1[8], oi0[8], oi1[8];
#pragma unroll
    for (int i = 0; i < 8; i++) {
        float c = sc[b8 + i];
        float s = ss[b8 + i];
        or0[i] = fmaf(c, re0[i],  s * im1[i]);
        oi0[i] = fmaf(c, im0[i], -s * re1[i]);
        or1[i] = fmaf(c, re1[i],  s * im0[i]);
        oi1[i] = fmaf(c, im1[i], -s * re0[i]);
    }

    stg256(out + t * 8u,                 or0);
    stg256(out + (t + H8) * 8u,          or1);
    stg256(out + (2u * H8 + t) * 8u,     oi0);
    stg256(out + (3u * H8 + t) * 8u,     oi1);
}

extern "C" void kernel_launch(void* const* d_in, const int* in_sizes, int n_in,
                              void* d_out, int out_size) {
    const float* theta = (const float*)d_in[0];
    const float* re    = (const float*)d_in[1];
    const float* im    = (const float*)d_in[2];
    float* out         = (float*)d_out;

    rot_kernel<<<H8 / TPB, TPB>>>(theta, re, im, out);
}

// round 14
// speedup vs baseline: 1.0020x; 1.0020x over previous
#include <cuda_runtime.h>

// Problem constants
#define DIM   (1 << 22)        // 2^22 = 4194304
#define BATCH 16
#define H8    ((DIM / 2) * BATCH / 8)   // 4194304 float8s per half-state
#define TPB   256                        // best-measured config

// 256-bit global streaming load (evict-first) / default store
// (sm_100+/sm_103a: LDG.E.256 / STG.E.256).
__device__ __forceinline__ void ldg256_cs(const float* __restrict__ p, float v[8]) {
    asm("ld.global.cs.v8.f32 {%0,%1,%2,%3,%4,%5,%6,%7}, [%8];"
        : "=f"(v[0]), "=f"(v[1]), "=f"(v[2]), "=f"(v[3]),
          "=f"(v[4]), "=f"(v[5]), "=f"(v[6]), "=f"(v[7])
        : "l"(p));
}
__device__ __forceinline__ void stg256(float* p, const float v[8]) {
    asm volatile("st.global.v8.f32 [%0], {%1,%2,%3,%4,%5,%6,%7,%8};"
        :: "l"(p),
           "f"(v[0]), "f"(v[1]), "f"(v[2]), "f"(v[3]),
           "f"(v[4]), "f"(v[5]), "f"(v[6]), "f"(v[7])
        : "memory");
}

// FINAL KERNEL — session optimum, converged after 13 rounds.
//
// RX(theta_b) on qubit 0 (MSB axis) applied to a (DIM, BATCH) complex state
// stored as separate re/im planes; output is stacked (re, im) planes.
// Pure 1:1 read/write stream: 536 MB in + 536 MB out at ~6.75 TB/s (85% of
// 8 TB/s HBM3e spec) — the read/write bus-turnaround roofline. Verified
// insensitive to: occupancy (37-63%), per-thread MLP (4-8), vector width
// (128/256-bit), block size (128/256), work-per-thread, index width.
// Store coherence is the only sensitive knob: default stores win; .cs/.wt
// stores cost 1.5-2.5 us in LTS handling. .cs loads are neutral-to-positive
// (zero-reuse inputs skip L2 retention). Four repeat runs of this exact
// config: kernel 150.0-151.4 us, total 157.73 +/- 0.07 us (noise floor).
//
// Thread t owns one float8 (8 of the 16 batch entries) of row j in the lower
// half, paired with row j + DIM/2. 4x LDG.256 front-batched and overlapped
// with the 16-element cos/sin broadcast, then 4x STG.256. All index math is
// 32-bit (each array is 256 MB; byte offsets < 2^31).
//
// Memory layout (float8 index space, H = H8):
//   inputs : re[t], re[t+H], im[t], im[t+H]
//   outputs: out_re lower = out[t], out_re upper = out[t+H]
//            out_im lower = out[2H+t], out_im upper = out[3H+t]
__global__ __launch_bounds__(TPB) void rot_kernel(
    const float* __restrict__ theta,
    const float* __restrict__ re,
    const float* __restrict__ im,
    float* __restrict__ out)
{
    __shared__ float sc[BATCH];
    __shared__ float ss[BATCH];

    unsigned t = blockIdx.x * TPB + threadIdx.x;   // float8 index, < 2^22

    // 4 independent 256-bit evict-first loads issued first
    // (latency overlapped with trig + barrier below)
    float re0[8], re1[8], im0[8], im1[8];
    ldg256_cs(re + t * 8u,             re0);
    ldg256_cs(re + (t + H8) * 8u,      re1);
    ldg256_cs(im + t * 8u,             im0);
    ldg256_cs(im + (t + H8) * 8u,      im1);

    if (threadIdx.x < BATCH) {
        float th = theta[threadIdx.x] * 0.5f;  // L2-resident after first wave
        sc[threadIdx.x] = cosf(th);
        ss[threadIdx.x] = sinf(th);
    }
    __syncthreads();

    int b8 = (int)(t & 1u) * 8;  // which float8 within the 16-wide batch row

    float or0[8], or1[8], oi0[8], oi1[8];
#pragma unroll
    for (int i = 0; i < 8; i++) {
        float c = sc[b8 + i];
        float s = ss[b8 + i];
        or0[i] = fmaf(c, re0[i],  s * im1[i]);
        oi0[i] = fmaf(c, im0[i], -s * re1[i]);
        or1[i] = fmaf(c, re1[i],  s * im0[i]);
        oi1[i] = fmaf(c, im1[i], -s * re0[i]);
    }

    stg256(out + t * 8u,                 or0);
    stg256(out + (t + H8) * 8u,          or1);
    stg256(out + (2u * H8 + t) * 8u,     oi0);
    stg256(out + (3u * H8 + t) * 8u,     oi1);
}

extern "C" void kernel_launch(void* const* d_in, const int* in_sizes, int n_in,
                              void* d_out, int out_size) {
    const float* theta = (const float*)d_in[0];
    const float* re    = (const float*)d_in[1];
    const float* im    = (const float*)d_in[2];
    float* out         = (float*)d_out;

    rot_kernel<<<H8 / TPB, TPB>>>(theta, re, im, out);
}

// round 15
// speedup vs baseline: 1.0026x; 1.0006x over previous
#include <cuda_runtime.h>

// Problem constants
#define DIM   (1 << 22)        // 2^22 = 4194304
#define BATCH 16
#define H8    ((DIM / 2) * BATCH / 8)   // 4194304 float8s per half-state
#define TPB   256                        // best-measured config

// 256-bit global streaming load (evict-first) / default store
// (sm_100+/sm_103a: LDG.E.256 / STG.E.256).
__device__ __forceinline__ void ldg256_cs(const float* __restrict__ p, float v[8]) {
    asm("ld.global.cs.v8.f32 {%0,%1,%2,%3,%4,%5,%6,%7}, [%8];"
        : "=f"(v[0]), "=f"(v[1]), "=f"(v[2]), "=f"(v[3]),
          "=f"(v[4]), "=f"(v[5]), "=f"(v[6]), "=f"(v[7])
        : "l"(p));
}
__device__ __forceinline__ void stg256(float* p, const float v[8]) {
    asm volatile("st.global.v8.f32 [%0], {%1,%2,%3,%4,%5,%6,%7,%8};"
        :: "l"(p),
           "f"(v[0]), "f"(v[1]), "f"(v[2]), "f"(v[3]),
           "f"(v[4]), "f"(v[5]), "f"(v[6]), "f"(v[7])
        : "memory");
}

// FINAL KERNEL — session optimum, converged after 14 rounds.
//
// RX(theta_b) on qubit 0 (MSB axis) applied to a (DIM, BATCH) complex state
// stored as separate re/im planes; output is stacked (re, im) planes.
// Pure 1:1 read/write stream: 536 MB in + 536 MB out at ~6.75 TB/s (85% of
// 8 TB/s HBM3e spec) — the read/write bus-turnaround roofline. Verified
// insensitive to: occupancy (37-63%), per-thread MLP (4-8), vector width
// (128/256-bit), block size (128/256), work-per-thread, index width.
// Store coherence is the only sensitive knob: default stores win; .cs/.wt
// stores cost 1.5-2.5 us in LTS handling. .cs loads are neutral-to-positive
// (zero-reuse inputs skip L2 retention). Five repeat runs of this exact
// config: kernel 150.0-151.8 us, total 157.44-157.76 us (noise floor).
//
// Thread t owns one float8 (8 of the 16 batch entries) of row j in the lower
// half, paired with row j + DIM/2. 4x LDG.256 front-batched and overlapped
// with the 16-element cos/sin broadcast, then 4x STG.256. All index math is
// 32-bit (each array is 256 MB; byte offsets < 2^31).
//
// Memory layout (float8 index space, H = H8):
//   inputs : re[t], re[t+H], im[t], im[t+H]
//   outputs: out_re lower = out[t], out_re upper = out[t+H]
//            out_im lower = out[2H+t], out_im upper = out[3H+t]
__global__ __launch_bounds__(TPB) void rot_kernel(
    const float* __restrict__ theta,
    const float* __restrict__ re,
    const float* __restrict__ im,
    float* __restrict__ out)
{
    __shared__ float sc[BATCH];
    __shared__ float ss[BATCH];

    unsigned t = blockIdx.x * TPB + threadIdx.x;   // float8 index, < 2^22

    // 4 independent 256-bit evict-first loads issued first
    // (latency overlapped with trig + barrier below)
    float re0[8], re1[8], im0[8], im1[8];
    ldg256_cs(re + t * 8u,             re0);
    ldg256_cs(re + (t + H8) * 8u,      re1);
    ldg256_cs(im + t * 8u,             im0);
    ldg256_cs(im + (t + H8) * 8u,      im1);

    if (threadIdx.x < BATCH) {
        float th = theta[threadIdx.x] * 0.5f;  // L2-resident after first wave
        sc[threadIdx.x] = cosf(th);
        ss[threadIdx.x] = sinf(th);
    }
    __syncthreads();

    int b8 = (int)(t & 1u) * 8;  // which float8 within the 16-wide batch row

    float or0[8], or1[8], oi0[8], oi1[8];
#pragma unroll
    for (int i = 0; i < 8; i++) {
        float c = sc[b8 + i];
        float s = ss[b8 + i];
        or0[i] = fmaf(c, re0[i],  s * im1[i]);
        oi0[i] = fmaf(c, im0[i], -s * re1[i]);
        or1[i] = fmaf(c, re1[i],  s * im0[i]);
        oi1[i] = fmaf(c, im1[i], -s * re0[i]);
    }

    stg256(out + t * 8u,                 or0);
    stg256(out + (t + H8) * 8u,          or1);
    stg256(out + (2u * H8 + t) * 8u,     oi0);
    stg256(out + (3u * H8 + t) * 8u,     oi1);
}

extern "C" void kernel_launch(void* const* d_in, const int* in_sizes, int n_in,
                              void* d_out, int out_size) {
    const float* theta = (const float*)d_in[0];
    const float* re    = (const float*)d_in[1];
    const float* im    = (const float*)d_in[2];
    float* out         = (float*)d_out;

    rot_kernel<<<H8 / TPB, TPB>>>(theta, re, im, out);
}